// round 16
// baseline (speedup 1.0000x reference)
#include <cuda_runtime.h>
#include <math.h>

#define EDGES 65536
#define NATOM 2048
#define KTOT 69
#define KPAD 84          // padded k-slots: 12 comp-pure groups of 7
#define NFEAT 216
#define NELEM 94
#define EMBD 16
#define H1D 256
#define H2D 128
#define MAXG 384         // 8-atom species groups: <= 94 + 2048/8 = 350
#define GATOMS 8
#define GPADF 10         // k_head row pad: 10 floats (8B aligned rows)
#define TILE 32
#define PAD 34           // k_atom smem row pad

// k_atom dynamic smem: two (sr+sg) buffers + sgi
#define BUFSZ ((120 + KPAD) * PAD)
#define SG_OFF (120 * PAD)
#define SGI_OFF (2 * BUFSZ)
#define SMEM_ATOM_FLOATS (SGI_OFF + 24 * KPAD)
#define SMEM_ATOM_BYTES (SMEM_ATOM_FLOATS * 4)

// k_edge smem layout
#define OFF_W1   0
#define OFF_B1   1536
#define OFF_BAS  1600
#define OFF_B2   4768
#define OFF_H    4888
#define EPAD     132
#define SMEM_EDGE_FLOATS 13336
#define SMEM_EDGE_BYTES (SMEM_EDGE_FLOATS * 4)

// ---------------- scratch ----------------
__device__ __align__(16) float d_radialT[120 * EDGES];
__device__ __align__(16) float d_gijT[KTOT * EDGES];
__device__ __align__(16) float d_feat[NATOM * NFEAT];
__device__ float d_embS[NELEM * EMBD];
__device__ __align__(16) float d_B[(size_t)NELEM * NFEAT * H1D]; // [s][f][o]
__device__ int   d_seg[NATOM + 1];
__device__ int   d_atom_order[NATOM];
__device__ int   d_grp_s[MAXG], d_grp_start[MAXG], d_grp_cnt[MAXG];
__device__ int   d_ngroups;
__device__ double d_partial[MAXG];

// ---------------- packed fp32x2 helpers ----------------
typedef unsigned long long u64;

__device__ __forceinline__ u64 splat2(float v) {
    u64 r; unsigned int u = __float_as_uint(v);
    asm("mov.b64 %0, {%1, %1};" : "=l"(r) : "r"(u));
    return r;
}
__device__ __forceinline__ void unpack2(u64 v, float& a, float& b) {
    unsigned int x, y;
    asm("mov.b64 {%0, %1}, %2;" : "=r"(x), "=r"(y) : "l"(v));
    a = __uint_as_float(x); b = __uint_as_float(y);
}
__device__ __forceinline__ void fma2(u64& d, u64 a, u64 b) {
    asm("fma.rn.f32x2 %0, %1, %2, %0;" : "+l"(d) : "l"(a), "l"(b));
}

__device__ __forceinline__ float silu(float x) {
    return __fdividef(x, 1.0f + __expf(-x));
}

__device__ constexpr float ffact(int n) {
    return (n <= 1) ? 1.0f : (float)n * ffact(n - 1);
}

// ============================================================================
// k_edge: block GEMM + fused segment-start fill + angular factors.
// ============================================================================
__global__ void __launch_bounds__(256, 3) k_edge(
    const float* __restrict__ rij,
    const float* __restrict__ Wr1, const float* __restrict__ br1,
    const float* __restrict__ Wr2, const float* __restrict__ br2,
    const int* __restrict__ fai)
{
    extern __shared__ __align__(16) float sm[];
    int tid = threadIdx.x;
    int eBase = blockIdx.x * 128;

    if (tid < 128) {
        int e = eBase + tid;

        {
            int f = fai[e];
            int fp = (e == 0) ? -1 : fai[e - 1];
            for (int a = fp + 1; a <= f; a++) d_seg[a] = e;
            if (e == EDGES - 1)
                for (int a = f + 1; a <= NATOM; a++) d_seg[a] = EDGES;
        }

        float x = rij[e * 3 + 0], y = rij[e * 3 + 1], z = rij[e * 3 + 2];
        float r = sqrtf(x * x + y * y + z * z);
        float inv = 1.0f / r;
        float ux = x * inv, uy = y * inv, uz = z * inv;

        float rc = fminf(r, 6.0f);
        float fc = 0.5f * (cospif(rc * (1.0f / 6.0f)) + 1.0f);

#pragma unroll
        for (int i = 0; i < 24; i++) {
            float d = r - (float)i * (6.0f / 23.0f);
            sm[OFF_BAS + i * EPAD + tid] = __expf(-d * d * 8.0f) * fc;
        }

        float px[5], py[5], pz[5];
        px[0]=1.0f; px[1]=ux+1e-12f; px[2]=px[1]*px[1]; px[3]=px[2]*px[1]; px[4]=px[2]*px[2];
        py[0]=1.0f; py[1]=uy+1e-12f; py[2]=py[1]*py[1]; py[3]=py[2]*py[1]; py[4]=py[2]*py[2];
        pz[0]=1.0f; pz[1]=uz+1e-12f; pz[2]=pz[1]*pz[1]; pz[3]=pz[2]*pz[1]; pz[4]=pz[2]*pz[2];
        int k = 0;
#pragma unroll
        for (int zz = 1; zz <= 4; zz++) {
#pragma unroll
            for (int n = 0; n <= zz; n++) {
#pragma unroll
                for (int lx = 0; lx <= n; lx++) {
#pragma unroll
                    for (int ly = 0; ly <= n - lx; ly++) {
                        int lz = n - lx - ly;
                        float fn = ffact(zz) / (ffact(zz - n) * ffact(lx) * ffact(ly) * ffact(lz));
                        d_gijT[(size_t)k * EDGES + e] = px[lx] * py[ly] * pz[lz] * fn;
                        k++;
                    }
                }
            }
        }
    } else {
        int t = tid - 128;
        for (int i = t; i < 24 * 64; i += 128) sm[OFF_W1 + i] = Wr1[i];
        if (t < 64)  sm[OFF_B1 + t] = br1[t];
        if (t < 120) sm[OFF_B2 + t] = br2[t];
    }
    __syncthreads();

    // phase B: layer1 GEMM 24->64
    {
        int ot = tid >> 4;
        int et = tid & 15;
        int o0 = ot * 4, e0 = et * 8;

        u64 acc[4][4];
#pragma unroll
        for (int i = 0; i < 4; i++) {
            u64 b = splat2(sm[OFF_B1 + o0 + i]);
#pragma unroll
            for (int p = 0; p < 4; p++) acc[i][p] = b;
        }

#pragma unroll 8
        for (int k = 0; k < 24; k++) {
            float4 w = *(const float4*)&sm[OFF_W1 + k * 64 + o0];
            const u64* bp = (const u64*)&sm[OFF_BAS + k * EPAD + e0];
            u64 b0 = bp[0], b1 = bp[1], b2 = bp[2], b3 = bp[3];
            u64 w0 = splat2(w.x), w1 = splat2(w.y), w2 = splat2(w.z), w3 = splat2(w.w);
            fma2(acc[0][0], b0, w0); fma2(acc[0][1], b1, w0); fma2(acc[0][2], b2, w0); fma2(acc[0][3], b3, w0);
            fma2(acc[1][0], b0, w1); fma2(acc[1][1], b1, w1); fma2(acc[1][2], b2, w1); fma2(acc[1][3], b3, w1);
            fma2(acc[2][0], b0, w2); fma2(acc[2][1], b1, w2); fma2(acc[2][2], b2, w2); fma2(acc[2][3], b3, w2);
            fma2(acc[3][0], b0, w3); fma2(acc[3][1], b1, w3); fma2(acc[3][2], b2, w3); fma2(acc[3][3], b3, w3);
        }

#pragma unroll
        for (int i = 0; i < 4; i++) {
#pragma unroll
            for (int p = 0; p < 4; p++) {
                float lo, hi; unpack2(acc[i][p], lo, hi);
                float2 v = { silu(lo), silu(hi) };
                *(float2*)&sm[OFF_H + (o0 + i) * EPAD + e0 + 2 * p] = v;
            }
        }
    }

    // phase C: layer2 GEMM 64->120, two output-half passes, W2 chunked
    {
        int ot = tid >> 4;
        int et = tid & 15;
        int o0 = ot * 8, e0 = et * 8;
        bool act = (tid < 240);

#pragma unroll 1
        for (int half = 0; half < 2; half++) {
            int oh = o0 + half * 4;
            u64 acc[4][4];
            if (act) {
#pragma unroll
                for (int i = 0; i < 4; i++) {
                    u64 b = splat2(sm[OFF_B2 + oh + i]);
#pragma unroll
                    for (int p = 0; p < 4; p++) acc[i][p] = b;
                }
            }

#pragma unroll 1
            for (int chunk = 0; chunk < 2; chunk++) {
                __syncthreads();
#pragma unroll
                for (int q = 0; q < 15; q++) {
                    int i = tid + q * 256;
                    sm[i] = Wr2[chunk * 32 * 120 + i];
                }
                __syncthreads();

                if (act) {
#pragma unroll 4
                    for (int j = 0; j < 32; j++) {
                        float4 w = *(const float4*)&sm[j * 120 + oh];
                        const u64* hp = (const u64*)&sm[OFF_H + (chunk * 32 + j) * EPAD + e0];
                        u64 h0 = hp[0], h1 = hp[1], h2 = hp[2], h3 = hp[3];
                        u64 ws;
                        ws = splat2(w.x); fma2(acc[0][0], h0, ws); fma2(acc[0][1], h1, ws); fma2(acc[0][2], h2, ws); fma2(acc[0][3], h3, ws);
                        ws = splat2(w.y); fma2(acc[1][0], h0, ws); fma2(acc[1][1], h1, ws); fma2(acc[1][2], h2, ws); fma2(acc[1][3], h3, ws);
                        ws = splat2(w.z); fma2(acc[2][0], h0, ws); fma2(acc[2][1], h1, ws); fma2(acc[2][2], h2, ws); fma2(acc[2][3], h3, ws);
                        ws = splat2(w.w); fma2(acc[3][0], h0, ws); fma2(acc[3][1], h1, ws); fma2(acc[3][2], h2, ws); fma2(acc[3][3], h3, ws);
                    }
                }
            }

            if (act) {
#pragma unroll
                for (int i = 0; i < 4; i++) {
                    float* row = &d_radialT[(size_t)(oh + i) * EDGES + eBase + e0];
#pragma unroll
                    for (int p = 0; p < 4; p++) {
                        float lo, hi; unpack2(acc[i][p], lo, hi);
                        float2 v = { silu(lo), silu(hi) };
                        *(float2*)&row[2 * p] = v;
                    }
                }
            }
        }
    }
}

// ============================================================================
// k_atom: double-buffered software pipeline (R15 version, measured 36.8us).
// ============================================================================
template <int Z>
__device__ __forceinline__ float zsum(const float* sgi, int rad, int sflag, int koff) {
    float sum = 0.0f;
    int idx = 0;
#pragma unroll
    for (int n = 0; n <= Z; n++) {
        float lam = (n & 1) ? -1.0f : 1.0f;
#pragma unroll
        for (int lx = 0; lx <= n; lx++) {
#pragma unroll
            for (int ly = 0; ly <= n - lx; ly++) {
                float g = sgi[rad * KPAD + koff + idx];
                float g2 = g * g;
                sum += sflag ? g2 * lam : g2;
                idx++;
            }
        }
    }
    return sum * (1.0f / (float)(1 << (Z - 1)));
}

__device__ __forceinline__ void load_tile_regs(int tid, int e0, int hi,
                                               float* rl, float* gl)
{
#pragma unroll
    for (int s = 0; s < 30; s++) {
        int i = tid + s * 128;
        int m = i >> 5, ee = i & 31;
        int e = e0 + ee;
        rl[s] = (e < hi) ? d_radialT[(size_t)m * EDGES + e] : 0.0f;
    }
#pragma unroll
    for (int s = 0; s < 21; s++) {
        int i = tid + s * 128;
        int kp = i >> 5, ee = i & 31;
        int e = e0 + ee;
        float v = 0.0f;
        if (e < hi) {
            if (kp < 4)       v = d_gijT[(size_t)kp * EDGES + e];
            else if (kp < 7)  v = 0.0f;
            else if (kp < 17) v = d_gijT[(size_t)(kp - 3) * EDGES + e];
            else if (kp < 21) v = 0.0f;
            else if (kp < 41) v = d_gijT[(size_t)(kp - 7) * EDGES + e];
            else if (kp < 42) v = 0.0f;
            else if (kp < 77) v = d_gijT[(size_t)(kp - 8) * EDGES + e];
            else if (kp == 77) v = 1.0f;
        } else if (kp == 77) {
            v = 1.0f;
        }
        gl[s] = v;
    }
}

__device__ __forceinline__ void store_tile_regs(int tid, float* buf,
                                                const float* rl, const float* gl)
{
#pragma unroll
    for (int s = 0; s < 30; s++) {
        int i = tid + s * 128;
        int m = i >> 5, ee = i & 31;
        buf[m * PAD + ee] = rl[s];
    }
#pragma unroll
    for (int s = 0; s < 21; s++) {
        int i = tid + s * 128;
        int kp = i >> 5, ee = i & 31;
        buf[SG_OFF + kp * PAD + ee] = gl[s];
    }
}

__global__ void __launch_bounds__(128) k_atom()
{
    extern __shared__ __align__(16) float dsm[];
    float* sgi = &dsm[SGI_OFF];

    int a = blockIdx.x;
    int tid = threadIdx.x;
    int lo = d_seg[a], hi = d_seg[a + 1];

    int kg = tid / 6;
    int rg = tid - kg * 6;
    int comp = (kg == 0) ? 1 : (kg < 3) ? 2 : (kg < 6) ? 3 : ((kg < 11) ? 4 : 0);
    bool compute = (tid < 72);

    int rrow[4], grow[7];
#pragma unroll
    for (int i = 0; i < 4; i++) rrow[i] = ((rg * 4 + i) * 5 + comp) * PAD;
#pragma unroll
    for (int j = 0; j < 7; j++) grow[j] = SG_OFF + (kg * 7 + j) * PAD;

    u64 acc[28];
#pragma unroll
    for (int q = 0; q < 28; q++) acc[q] = 0ull;

    {
        float rl[30], gl[21];
        load_tile_regs(tid, lo, hi, rl, gl);
        store_tile_regs(tid, &dsm[0], rl, gl);
    }
    __syncthreads();

    int buf = 0;
    for (int e0 = lo; e0 < hi; e0 += TILE) {
        float* cur = &dsm[buf * BUFSZ];
        float* nxt = &dsm[(buf ^ 1) * BUFSZ];
        int en = e0 + TILE;
        bool more = en < hi;

        float rl[30], gl[21];
        if (more) load_tile_regs(tid, en, hi, rl, gl);

        if (compute) {
#pragma unroll
            for (int p = 0; p < 16; p++) {
                u64 rv[4], gv[7];
#pragma unroll
                for (int i = 0; i < 4; i++) rv[i] = *(const u64*)&cur[rrow[i] + 2 * p];
#pragma unroll
                for (int j = 0; j < 7; j++) gv[j] = *(const u64*)&cur[grow[j] + 2 * p];
#pragma unroll
                for (int i = 0; i < 4; i++)
#pragma unroll
                    for (int j = 0; j < 7; j++)
                        fma2(acc[i * 7 + j], rv[i], gv[j]);
            }
        }

        if (more) store_tile_regs(tid, nxt, rl, gl);
        __syncthreads();
        buf ^= 1;
    }

    if (compute) {
#pragma unroll
        for (int i = 0; i < 4; i++) {
#pragma unroll
            for (int j = 0; j < 7; j++) {
                float l0, l1; unpack2(acc[i * 7 + j], l0, l1);
                sgi[(rg * 4 + i) * KPAD + kg * 7 + j] = l0 + l1;
            }
        }
    }
    __syncthreads();

    for (int f = tid; f < NFEAT; f += 128) {
        float v;
        if (f < 24) v = sgi[f * KPAD + 77];
        else {
            int t = f - 24;
            int iz = t / 48;
            int sflag = (t / 24) & 1;
            int rad = t % 24;
            if (iz == 0)      v = zsum<1>(sgi, rad, sflag, 0);
            else if (iz == 1) v = zsum<2>(sgi, rad, sflag, 7);
            else if (iz == 2) v = zsum<3>(sgi, rad, sflag, 21);
            else              v = zsum<4>(sgi, rad, sflag, 42);
        }
        d_feat[a * NFEAT + f] = v;
    }
}

// ============================================================================
// k_B: collapsed first-layer weights B[s][f][o] ; split over 4 species chunks
// ============================================================================
__global__ void __launch_bounds__(256) k_B(const float* __restrict__ Wa1)
{
    int f = blockIdx.x;
    int s0 = blockIdx.y * 24;
    int s1 = min(NELEM, s0 + 24);
    int tid = threadIdx.x;
    __shared__ float sW[16 * 256];
    __shared__ float sE[24 * EMBD];
    for (int i = tid; i < 16 * 256; i += 256) sW[i] = Wa1[(size_t)(f * 16) * 256 + i];
    for (int i = tid; i < (s1 - s0) * EMBD; i += 256) sE[i] = d_embS[s0 * EMBD + i];
    __syncthreads();
#pragma unroll 2
    for (int s = s0; s < s1; s++) {
        float acc = 0.0f;
#pragma unroll
        for (int m = 0; m < EMBD; m++) acc += sE[(s - s0) * EMBD + m] * sW[m * 256 + tid];
        d_B[((size_t)s * NFEAT + f) * H1D + tid] = acc;
    }
}

// ============================================================================
// k_group: species grouping (8-atom groups) + fused embedding + bitmap rank
// ============================================================================
__global__ void __launch_bounds__(1024) k_group(
    const int* __restrict__ sp,
    const float* __restrict__ Ws1, const float* __restrict__ bs1,
    const float* __restrict__ Ws2, const float* __restrict__ bs2)
{
    __shared__ int cnt[NELEM];
    __shared__ int off[NELEM];
    __shared__ int ssp[NATOM];
    __shared__ unsigned bm[NELEM][NATOM / 32];
    int tid = threadIdx.x;
    int wid = tid >> 5, lane = tid & 31;

    for (int s = wid; s < NELEM; s += 32) {
        float hh = silu(Ws1[s * 32 + lane] + bs1[lane]);
        int li = (lane < EMBD) ? lane : 0;
        float acc2 = bs2[li];
#pragma unroll
        for (int j = 0; j < 32; j++)
            acc2 += __shfl_sync(0xffffffffu, hh, j) * Ws2[j * EMBD + li];
        if (lane < EMBD) d_embS[s * EMBD + lane] = acc2;
    }

    if (tid < NELEM) cnt[tid] = 0;
    for (int i = tid; i < NELEM * (NATOM / 32); i += 1024)
        ((unsigned*)bm)[i] = 0u;
    for (int a = tid; a < NATOM; a += 1024) ssp[a] = sp[a];
    __syncthreads();
    for (int a = tid; a < NATOM; a += 1024) {
        int s = ssp[a];
        atomicAdd(&cnt[s], 1);
        atomicOr(&bm[s][a >> 5], 1u << (a & 31));
    }
    __syncthreads();
    if (tid == 0) {
        int o = 0, ng = 0;
        for (int s = 0; s < NELEM; s++) {
            off[s] = o;
            int c = cnt[s];
            for (int ch = 0; ch < c; ch += GATOMS) {
                d_grp_s[ng] = s; d_grp_start[ng] = o + ch;
                d_grp_cnt[ng] = min(GATOMS, c - ch); ng++;
            }
            o += c;
        }
        d_ngroups = ng;
    }
    for (int g = tid; g < MAXG; g += 1024) d_partial[g] = 0.0;
    __syncthreads();
    for (int a = tid; a < NATOM; a += 1024) {
        int s = ssp[a];
        int w = a >> 5;
        int r = 0;
        for (int j = 0; j < w; j++) r += __popc(bm[s][j]);
        r += __popc(bm[s][w] & ((1u << (a & 31)) - 1u));
        d_atom_order[off[s] + r] = a;
    }
}

// ============================================================================
// head MLP per 8-atom species group; atoms packed in f32x2 lanes (4 pairs)
// ============================================================================
__global__ void __launch_bounds__(256) k_head(
    const float* __restrict__ ba1,
    const float* __restrict__ Wa2, const float* __restrict__ ba2,
    const float* __restrict__ Wa3, const float* __restrict__ ba3)
{
    int g = blockIdx.x;
    if (g >= d_ngroups) return;
    int tid = threadIdx.x;

    __shared__ __align__(16) float sfeatT[NFEAT * GPADF];   // [f][atom]
    __shared__ __align__(16) float sh1T[H1D * GPADF];       // [j][atom]
    __shared__ __align__(16) float sh2T[H2D * GPADF];       // [o][atom]
    __shared__ double se[GATOMS];
    __shared__ int satom[GATOMS];

    int s = d_grp_s[g], start = d_grp_start[g], cnt = d_grp_cnt[g];
    if (tid < GATOMS) satom[tid] = (tid < cnt) ? d_atom_order[start + tid] : 0;
    __syncthreads();

    for (int i = tid; i < GATOMS * NFEAT; i += 256) {
        int al = i / NFEAT, f = i - al * NFEAT;
        sfeatT[f * GPADF + al] = (al < cnt) ? d_feat[(size_t)satom[al] * NFEAT + f] : 0.0f;
    }
    __syncthreads();

    // layer 1: 216 -> 256 ; thread = output neuron, 8 atoms as 4 pairs
    {
        u64 acc2[4];
        u64 binit = splat2(ba1[tid]);
#pragma unroll
        for (int p = 0; p < 4; p++) acc2[p] = binit;

        const float* Bs = &d_B[((size_t)s * NFEAT) * H1D + tid];
#pragma unroll 8
        for (int f = 0; f < NFEAT; f++) {
            u64 bw = splat2(__ldg(&Bs[(size_t)f * H1D]));
            const u64* fp = (const u64*)&sfeatT[f * GPADF];
#pragma unroll
            for (int p = 0; p < 4; p++) fma2(acc2[p], fp[p], bw);
        }
#pragma unroll
        for (int p = 0; p < 4; p++) {
            float lo, hi; unpack2(acc2[p], lo, hi);
            sh1T[tid * GPADF + 2 * p]     = silu(lo);
            sh1T[tid * GPADF + 2 * p + 1] = silu(hi);
        }
    }
    __syncthreads();

    // layer 2: 256 -> 128 ; thread = (out o2, atom-half of 4)
    {
        int o2 = tid & 127;
        int half = tid >> 7;
        u64 acc2[2];
        u64 binit = splat2(ba2[o2]);
        acc2[0] = binit; acc2[1] = binit;
#pragma unroll 8
        for (int j = 0; j < H1D; j++) {
            u64 w = splat2(__ldg(&Wa2[j * H2D + o2]));
            const u64* hp = (const u64*)&sh1T[j * GPADF + half * 4];
            fma2(acc2[0], hp[0], w); fma2(acc2[1], hp[1], w);
        }
#pragma unroll
        for (int p = 0; p < 2; p++) {
            float lo, hi; unpack2(acc2[p], lo, hi);
            sh2T[o2 * GPADF + half * 4 + 2 * p]     = silu(lo);
            sh2T[o2 * GPADF + half * 4 + 2 * p + 1] = silu(hi);
        }
    }
    __syncthreads();

    if (tid < GATOMS) {
        double ev = 0.0;
        if (tid < cnt) {
            float e3 = ba3[0];
#pragma unroll 4
            for (int j = 0; j < H2D; j++) e3 += sh2T[j * GPADF + tid] * Wa3[j];
            ev = (double)e3;
        }
        se[tid] = ev;
    }
    __syncthreads();
    if (tid == 0) {
        double ssum = 0.0;
        for (int i = 0; i < GATOMS; i++) ssum += se[i];
        d_partial[g] = ssum;
    }
}

__global__ void k_final(float* out) {
    int lane = threadIdx.x;
    double s = 0.0;
    for (int g = lane; g < MAXG; g += 32) s += d_partial[g];
#pragma unroll
    for (int o = 16; o > 0; o >>= 1) s += __shfl_down_sync(0xffffffffu, s, o);
    if (lane == 0) out[0] = (float)s;
}

// ============================================================================
extern "C" void kernel_launch(void* const* d_in, const int* in_sizes, int n_in,
                              void* d_out, int out_size)
{
    const float* rij = (const float*)d_in[0];
    const float* Wr1 = (const float*)d_in[1];
    const float* br1 = (const float*)d_in[2];
    const float* Wr2 = (const float*)d_in[3];
    const float* br2 = (const float*)d_in[4];
    const float* Ws1 = (const float*)d_in[5];
    const float* bs1 = (const float*)d_in[6];
    const float* Ws2 = (const float*)d_in[7];
    const float* bs2 = (const float*)d_in[8];
    const float* Wa1 = (const float*)d_in[9];
    const float* ba1 = (const float*)d_in[10];
    const float* Wa2 = (const float*)d_in[11];
    const float* ba2 = (const float*)d_in[12];
    const float* Wa3 = (const float*)d_in[13];
    const float* ba3 = (const float*)d_in[14];
    const int* fai = (const int*)d_in[15];
    const int* species = (const int*)d_in[16];
    float* out = (float*)d_out;

    static int smem_set = 0;
    if (!smem_set) {
        cudaFuncSetAttribute(k_edge, cudaFuncAttributeMaxDynamicSharedMemorySize,
                             SMEM_EDGE_BYTES);
        cudaFuncSetAttribute(k_atom, cudaFuncAttributeMaxDynamicSharedMemorySize,
                             SMEM_ATOM_BYTES);
        smem_set = 1;
    }

    k_group<<<1, 1024>>>(species, Ws1, bs1, Ws2, bs2);
    k_edge<<<EDGES / 128, 256, SMEM_EDGE_BYTES>>>(rij, Wr1, br1, Wr2, br2, fai);
    k_B<<<dim3(NFEAT, 4), 256>>>(Wa1);
    k_atom<<<NATOM, 128, SMEM_ATOM_BYTES>>>();
    k_head<<<MAXG, 256>>>(ba1, Wa2, ba2, Wa3, ba3);
    k_final<<<1, 32>>>(out);
}

// round 17
// speedup vs baseline: 1.1609x; 1.1609x over previous
#include <cuda_runtime.h>
#include <math.h>

#define EDGES 65536
#define NATOM 2048
#define KTOT 69
#define KPAD 84          // padded k-slots: 12 comp-pure groups of 7
#define NFEAT 216
#define NELEM 94
#define EMBD 16
#define H1D 256
#define H2D 128
#define MAXG 384         // 8-atom species groups
#define GATOMS 8
#define GPADF 10         // k_head row pad: 10 floats (8B aligned rows)
#define TILE 32
#define PAD 34           // k_atom smem row pad

// k_atom dynamic smem: two (sr+sg) buffers + sgi
#define BUFSZ ((120 + KPAD) * PAD)
#define SG_OFF (120 * PAD)
#define SGI_OFF (2 * BUFSZ)
#define SMEM_ATOM_FLOATS (SGI_OFF + 24 * KPAD)
#define SMEM_ATOM_BYTES (SMEM_ATOM_FLOATS * 4)

// k_edge smem layout
#define OFF_W1   0
#define OFF_B1   1536
#define OFF_BAS  1600
#define OFF_B2   4768
#define OFF_H    4888
#define EPAD     132
#define SMEM_EDGE_FLOATS 13336
#define SMEM_EDGE_BYTES (SMEM_EDGE_FLOATS * 4)

// ---------------- scratch ----------------
__device__ __align__(16) float d_radialT[120 * EDGES];
__device__ __align__(16) float d_gijT[KTOT * EDGES];
__device__ __align__(16) float d_feat[NATOM * NFEAT];
__device__ float d_embS[NELEM * EMBD];
__device__ __align__(16) float d_B[(size_t)NELEM * NFEAT * H1D]; // [s][f][o]
__device__ int   d_seg[NATOM + 1];
__device__ int   d_atom_order[NATOM];
__device__ int   d_grp_s[MAXG], d_grp_start[MAXG], d_grp_cnt[MAXG];
__device__ int   d_ngroups;
__device__ double d_partial[MAXG];

// ---------------- packed fp32x2 helpers ----------------
typedef unsigned long long u64;

__device__ __forceinline__ u64 splat2(float v) {
    u64 r; unsigned int u = __float_as_uint(v);
    asm("mov.b64 %0, {%1, %1};" : "=l"(r) : "r"(u));
    return r;
}
__device__ __forceinline__ void unpack2(u64 v, float& a, float& b) {
    unsigned int x, y;
    asm("mov.b64 {%0, %1}, %2;" : "=r"(x), "=r"(y) : "l"(v));
    a = __uint_as_float(x); b = __uint_as_float(y);
}
__device__ __forceinline__ void fma2(u64& d, u64 a, u64 b) {
    asm("fma.rn.f32x2 %0, %1, %2, %0;" : "+l"(d) : "l"(a), "l"(b));
}

__device__ __forceinline__ float silu(float x) {
    return __fdividef(x, 1.0f + __expf(-x));
}

__device__ constexpr float ffact(int n) {
    return (n <= 1) ? 1.0f : (float)n * ffact(n - 1);
}

// ============================================================================
// k_edge: block GEMM + fused segment-start fill + angular factors.
// ============================================================================
__global__ void __launch_bounds__(256, 3) k_edge(
    const float* __restrict__ rij,
    const float* __restrict__ Wr1, const float* __restrict__ br1,
    const float* __restrict__ Wr2, const float* __restrict__ br2,
    const int* __restrict__ fai)
{
    extern __shared__ __align__(16) float sm[];
    int tid = threadIdx.x;
    int eBase = blockIdx.x * 128;

    if (tid < 128) {
        int e = eBase + tid;

        {
            int f = fai[e];
            int fp = (e == 0) ? -1 : fai[e - 1];
            for (int a = fp + 1; a <= f; a++) d_seg[a] = e;
            if (e == EDGES - 1)
                for (int a = f + 1; a <= NATOM; a++) d_seg[a] = EDGES;
        }

        float x = rij[e * 3 + 0], y = rij[e * 3 + 1], z = rij[e * 3 + 2];
        float r = sqrtf(x * x + y * y + z * z);
        float inv = 1.0f / r;
        float ux = x * inv, uy = y * inv, uz = z * inv;

        float rc = fminf(r, 6.0f);
        float fc = 0.5f * (cospif(rc * (1.0f / 6.0f)) + 1.0f);

#pragma unroll
        for (int i = 0; i < 24; i++) {
            float d = r - (float)i * (6.0f / 23.0f);
            sm[OFF_BAS + i * EPAD + tid] = __expf(-d * d * 8.0f) * fc;
        }

        float px[5], py[5], pz[5];
        px[0]=1.0f; px[1]=ux+1e-12f; px[2]=px[1]*px[1]; px[3]=px[2]*px[1]; px[4]=px[2]*px[2];
        py[0]=1.0f; py[1]=uy+1e-12f; py[2]=py[1]*py[1]; py[3]=py[2]*py[1]; py[4]=py[2]*py[2];
        pz[0]=1.0f; pz[1]=uz+1e-12f; pz[2]=pz[1]*pz[1]; pz[3]=pz[2]*pz[1]; pz[4]=pz[2]*pz[2];
        int k = 0;
#pragma unroll
        for (int zz = 1; zz <= 4; zz++) {
#pragma unroll
            for (int n = 0; n <= zz; n++) {
#pragma unroll
                for (int lx = 0; lx <= n; lx++) {
#pragma unroll
                    for (int ly = 0; ly <= n - lx; ly++) {
                        int lz = n - lx - ly;
                        float fn = ffact(zz) / (ffact(zz - n) * ffact(lx) * ffact(ly) * ffact(lz));
                        d_gijT[(size_t)k * EDGES + e] = px[lx] * py[ly] * pz[lz] * fn;
                        k++;
                    }
                }
            }
        }
    } else {
        int t = tid - 128;
        for (int i = t; i < 24 * 64; i += 128) sm[OFF_W1 + i] = Wr1[i];
        if (t < 64)  sm[OFF_B1 + t] = br1[t];
        if (t < 120) sm[OFF_B2 + t] = br2[t];
    }
    __syncthreads();

    // phase B: layer1 GEMM 24->64
    {
        int ot = tid >> 4;
        int et = tid & 15;
        int o0 = ot * 4, e0 = et * 8;

        u64 acc[4][4];
#pragma unroll
        for (int i = 0; i < 4; i++) {
            u64 b = splat2(sm[OFF_B1 + o0 + i]);
#pragma unroll
            for (int p = 0; p < 4; p++) acc[i][p] = b;
        }

#pragma unroll 8
        for (int k = 0; k < 24; k++) {
            float4 w = *(const float4*)&sm[OFF_W1 + k * 64 + o0];
            const u64* bp = (const u64*)&sm[OFF_BAS + k * EPAD + e0];
            u64 b0 = bp[0], b1 = bp[1], b2 = bp[2], b3 = bp[3];
            u64 w0 = splat2(w.x), w1 = splat2(w.y), w2 = splat2(w.z), w3 = splat2(w.w);
            fma2(acc[0][0], b0, w0); fma2(acc[0][1], b1, w0); fma2(acc[0][2], b2, w0); fma2(acc[0][3], b3, w0);
            fma2(acc[1][0], b0, w1); fma2(acc[1][1], b1, w1); fma2(acc[1][2], b2, w1); fma2(acc[1][3], b3, w1);
            fma2(acc[2][0], b0, w2); fma2(acc[2][1], b1, w2); fma2(acc[2][2], b2, w2); fma2(acc[2][3], b3, w2);
            fma2(acc[3][0], b0, w3); fma2(acc[3][1], b1, w3); fma2(acc[3][2], b2, w3); fma2(acc[3][3], b3, w3);
        }

#pragma unroll
        for (int i = 0; i < 4; i++) {
#pragma unroll
            for (int p = 0; p < 4; p++) {
                float lo, hi; unpack2(acc[i][p], lo, hi);
                float2 v = { silu(lo), silu(hi) };
                *(float2*)&sm[OFF_H + (o0 + i) * EPAD + e0 + 2 * p] = v;
            }
        }
    }

    // phase C: layer2 GEMM 64->120, two output-half passes, W2 chunked
    {
        int ot = tid >> 4;
        int et = tid & 15;
        int o0 = ot * 8, e0 = et * 8;
        bool act = (tid < 240);

#pragma unroll 1
        for (int half = 0; half < 2; half++) {
            int oh = o0 + half * 4;
            u64 acc[4][4];
            if (act) {
#pragma unroll
                for (int i = 0; i < 4; i++) {
                    u64 b = splat2(sm[OFF_B2 + oh + i]);
#pragma unroll
                    for (int p = 0; p < 4; p++) acc[i][p] = b;
                }
            }

#pragma unroll 1
            for (int chunk = 0; chunk < 2; chunk++) {
                __syncthreads();
#pragma unroll
                for (int q = 0; q < 15; q++) {
                    int i = tid + q * 256;
                    sm[i] = Wr2[chunk * 32 * 120 + i];
                }
                __syncthreads();

                if (act) {
#pragma unroll 4
                    for (int j = 0; j < 32; j++) {
                        float4 w = *(const float4*)&sm[j * 120 + oh];
                        const u64* hp = (const u64*)&sm[OFF_H + (chunk * 32 + j) * EPAD + e0];
                        u64 h0 = hp[0], h1 = hp[1], h2 = hp[2], h3 = hp[3];
                        u64 ws;
                        ws = splat2(w.x); fma2(acc[0][0], h0, ws); fma2(acc[0][1], h1, ws); fma2(acc[0][2], h2, ws); fma2(acc[0][3], h3, ws);
                        ws = splat2(w.y); fma2(acc[1][0], h0, ws); fma2(acc[1][1], h1, ws); fma2(acc[1][2], h2, ws); fma2(acc[1][3], h3, ws);
                        ws = splat2(w.z); fma2(acc[2][0], h0, ws); fma2(acc[2][1], h1, ws); fma2(acc[2][2], h2, ws); fma2(acc[2][3], h3, ws);
                        ws = splat2(w.w); fma2(acc[3][0], h0, ws); fma2(acc[3][1], h1, ws); fma2(acc[3][2], h2, ws); fma2(acc[3][3], h3, ws);
                    }
                }
            }

            if (act) {
#pragma unroll
                for (int i = 0; i < 4; i++) {
                    float* row = &d_radialT[(size_t)(oh + i) * EDGES + eBase + e0];
#pragma unroll
                    for (int p = 0; p < 4; p++) {
                        float lo, hi; unpack2(acc[i][p], lo, hi);
                        float2 v = { silu(lo), silu(hi) };
                        *(float2*)&row[2 * p] = v;
                    }
                }
            }
        }
    }
}

// ============================================================================
// k_atom: double-buffered software pipeline (measured 36.8us).
// ============================================================================
template <int Z>
__device__ __forceinline__ float zsum(const float* sgi, int rad, int sflag, int koff) {
    float sum = 0.0f;
    int idx = 0;
#pragma unroll
    for (int n = 0; n <= Z; n++) {
        float lam = (n & 1) ? -1.0f : 1.0f;
#pragma unroll
        for (int lx = 0; lx <= n; lx++) {
#pragma unroll
            for (int ly = 0; ly <= n - lx; ly++) {
                float g = sgi[rad * KPAD + koff + idx];
                float g2 = g * g;
                sum += sflag ? g2 * lam : g2;
                idx++;
            }
        }
    }
    return sum * (1.0f / (float)(1 << (Z - 1)));
}

__device__ __forceinline__ void load_tile_regs(int tid, int e0, int hi,
                                               float* rl, float* gl)
{
#pragma unroll
    for (int s = 0; s < 30; s++) {
        int i = tid + s * 128;
        int m = i >> 5, ee = i & 31;
        int e = e0 + ee;
        rl[s] = (e < hi) ? d_radialT[(size_t)m * EDGES + e] : 0.0f;
    }
#pragma unroll
    for (int s = 0; s < 21; s++) {
        int i = tid + s * 128;
        int kp = i >> 5, ee = i & 31;
        int e = e0 + ee;
        float v = 0.0f;
        if (e < hi) {
            if (kp < 4)       v = d_gijT[(size_t)kp * EDGES + e];
            else if (kp < 7)  v = 0.0f;
            else if (kp < 17) v = d_gijT[(size_t)(kp - 3) * EDGES + e];
            else if (kp < 21) v = 0.0f;
            else if (kp < 41) v = d_gijT[(size_t)(kp - 7) * EDGES + e];
            else if (kp < 42) v = 0.0f;
            else if (kp < 77) v = d_gijT[(size_t)(kp - 8) * EDGES + e];
            else if (kp == 77) v = 1.0f;
        } else if (kp == 77) {
            v = 1.0f;
        }
        gl[s] = v;
    }
}

__device__ __forceinline__ void store_tile_regs(int tid, float* buf,
                                                const float* rl, const float* gl)
{
#pragma unroll
    for (int s = 0; s < 30; s++) {
        int i = tid + s * 128;
        int m = i >> 5, ee = i & 31;
        buf[m * PAD + ee] = rl[s];
    }
#pragma unroll
    for (int s = 0; s < 21; s++) {
        int i = tid + s * 128;
        int kp = i >> 5, ee = i & 31;
        buf[SG_OFF + kp * PAD + ee] = gl[s];
    }
}

__global__ void __launch_bounds__(128) k_atom()
{
    extern __shared__ __align__(16) float dsm[];
    float* sgi = &dsm[SGI_OFF];

    int a = blockIdx.x;
    int tid = threadIdx.x;
    int lo = d_seg[a], hi = d_seg[a + 1];

    int kg = tid / 6;
    int rg = tid - kg * 6;
    int comp = (kg == 0) ? 1 : (kg < 3) ? 2 : (kg < 6) ? 3 : ((kg < 11) ? 4 : 0);
    bool compute = (tid < 72);

    int rrow[4], grow[7];
#pragma unroll
    for (int i = 0; i < 4; i++) rrow[i] = ((rg * 4 + i) * 5 + comp) * PAD;
#pragma unroll
    for (int j = 0; j < 7; j++) grow[j] = SG_OFF + (kg * 7 + j) * PAD;

    u64 acc[28];
#pragma unroll
    for (int q = 0; q < 28; q++) acc[q] = 0ull;

    {
        float rl[30], gl[21];
        load_tile_regs(tid, lo, hi, rl, gl);
        store_tile_regs(tid, &dsm[0], rl, gl);
    }
    __syncthreads();

    int buf = 0;
    for (int e0 = lo; e0 < hi; e0 += TILE) {
        float* cur = &dsm[buf * BUFSZ];
        float* nxt = &dsm[(buf ^ 1) * BUFSZ];
        int en = e0 + TILE;
        bool more = en < hi;

        float rl[30], gl[21];
        if (more) load_tile_regs(tid, en, hi, rl, gl);

        if (compute) {
#pragma unroll
            for (int p = 0; p < 16; p++) {
                u64 rv[4], gv[7];
#pragma unroll
                for (int i = 0; i < 4; i++) rv[i] = *(const u64*)&cur[rrow[i] + 2 * p];
#pragma unroll
                for (int j = 0; j < 7; j++) gv[j] = *(const u64*)&cur[grow[j] + 2 * p];
#pragma unroll
                for (int i = 0; i < 4; i++)
#pragma unroll
                    for (int j = 0; j < 7; j++)
                        fma2(acc[i * 7 + j], rv[i], gv[j]);
            }
        }

        if (more) store_tile_regs(tid, nxt, rl, gl);
        __syncthreads();
        buf ^= 1;
    }

    if (compute) {
#pragma unroll
        for (int i = 0; i < 4; i++) {
#pragma unroll
            for (int j = 0; j < 7; j++) {
                float l0, l1; unpack2(acc[i * 7 + j], l0, l1);
                sgi[(rg * 4 + i) * KPAD + kg * 7 + j] = l0 + l1;
            }
        }
    }
    __syncthreads();

    for (int f = tid; f < NFEAT; f += 128) {
        float v;
        if (f < 24) v = sgi[f * KPAD + 77];
        else {
            int t = f - 24;
            int iz = t / 48;
            int sflag = (t / 24) & 1;
            int rad = t % 24;
            if (iz == 0)      v = zsum<1>(sgi, rad, sflag, 0);
            else if (iz == 1) v = zsum<2>(sgi, rad, sflag, 7);
            else if (iz == 2) v = zsum<3>(sgi, rad, sflag, 21);
            else              v = zsum<4>(sgi, rad, sflag, 42);
        }
        d_feat[a * NFEAT + f] = v;
    }
}

// ============================================================================
// k_B: collapsed first-layer weights B[s][f][o] ; split over 4 species chunks
// ============================================================================
__global__ void __launch_bounds__(256) k_B(const float* __restrict__ Wa1)
{
    int f = blockIdx.x;
    int s0 = blockIdx.y * 24;
    int s1 = min(NELEM, s0 + 24);
    int tid = threadIdx.x;
    __shared__ float sW[16 * 256];
    __shared__ float sE[24 * EMBD];
    for (int i = tid; i < 16 * 256; i += 256) sW[i] = Wa1[(size_t)(f * 16) * 256 + i];
    for (int i = tid; i < (s1 - s0) * EMBD; i += 256) sE[i] = d_embS[s0 * EMBD + i];
    __syncthreads();
#pragma unroll 2
    for (int s = s0; s < s1; s++) {
        float acc = 0.0f;
#pragma unroll
        for (int m = 0; m < EMBD; m++) acc += sE[(s - s0) * EMBD + m] * sW[m * 256 + tid];
        d_B[((size_t)s * NFEAT + f) * H1D + tid] = acc;
    }
}

// ============================================================================
// k_group: species grouping (8-atom groups) + fused embedding + bitmap rank
// ============================================================================
__global__ void __launch_bounds__(1024) k_group(
    const int* __restrict__ sp,
    const float* __restrict__ Ws1, const float* __restrict__ bs1,
    const float* __restrict__ Ws2, const float* __restrict__ bs2)
{
    __shared__ int cnt[NELEM];
    __shared__ int off[NELEM];
    __shared__ int ssp[NATOM];
    __shared__ unsigned bm[NELEM][NATOM / 32];
    int tid = threadIdx.x;
    int wid = tid >> 5, lane = tid & 31;

    for (int s = wid; s < NELEM; s += 32) {
        float hh = silu(Ws1[s * 32 + lane] + bs1[lane]);
        int li = (lane < EMBD) ? lane : 0;
        float acc2 = bs2[li];
#pragma unroll
        for (int j = 0; j < 32; j++)
            acc2 += __shfl_sync(0xffffffffu, hh, j) * Ws2[j * EMBD + li];
        if (lane < EMBD) d_embS[s * EMBD + lane] = acc2;
    }

    if (tid < NELEM) cnt[tid] = 0;
    for (int i = tid; i < NELEM * (NATOM / 32); i += 1024)
        ((unsigned*)bm)[i] = 0u;
    for (int a = tid; a < NATOM; a += 1024) ssp[a] = sp[a];
    __syncthreads();
    for (int a = tid; a < NATOM; a += 1024) {
        int s = ssp[a];
        atomicAdd(&cnt[s], 1);
        atomicOr(&bm[s][a >> 5], 1u << (a & 31));
    }
    __syncthreads();
    if (tid == 0) {
        int o = 0, ng = 0;
        for (int s = 0; s < NELEM; s++) {
            off[s] = o;
            int c = cnt[s];
            for (int ch = 0; ch < c; ch += GATOMS) {
                d_grp_s[ng] = s; d_grp_start[ng] = o + ch;
                d_grp_cnt[ng] = min(GATOMS, c - ch); ng++;
            }
            o += c;
        }
        d_ngroups = ng;
    }
    for (int g = tid; g < MAXG; g += 1024) d_partial[g] = 0.0;
    __syncthreads();
    for (int a = tid; a < NATOM; a += 1024) {
        int s = ssp[a];
        int w = a >> 5;
        int r = 0;
        for (int j = 0; j < w; j++) r += __popc(bm[s][j]);
        r += __popc(bm[s][w] & ((1u << (a & 31)) - 1u));
        d_atom_order[off[s] + r] = a;
    }
}

// ============================================================================
// head MLP per 8-atom species group; atoms packed in f32x2 lanes
// ============================================================================
__global__ void __launch_bounds__(256) k_head(
    const float* __restrict__ ba1,
    const float* __restrict__ Wa2, const float* __restrict__ ba2,
    const float* __restrict__ Wa3, const float* __restrict__ ba3)
{
    int g = blockIdx.x;
    if (g >= d_ngroups) return;
    int tid = threadIdx.x;

    __shared__ __align__(16) float sfeatT[NFEAT * GPADF];
    __shared__ __align__(16) float sh1T[H1D * GPADF];
    __shared__ __align__(16) float sh2T[H2D * GPADF];
    __shared__ double se[GATOMS];
    __shared__ int satom[GATOMS];

    int s = d_grp_s[g], start = d_grp_start[g], cnt = d_grp_cnt[g];
    if (tid < GATOMS) satom[tid] = (tid < cnt) ? d_atom_order[start + tid] : 0;
    __syncthreads();

    for (int i = tid; i < GATOMS * NFEAT; i += 256) {
        int al = i / NFEAT, f = i - al * NFEAT;
        sfeatT[f * GPADF + al] = (al < cnt) ? d_feat[(size_t)satom[al] * NFEAT + f] : 0.0f;
    }
    __syncthreads();

    // layer 1: 216 -> 256
    {
        u64 acc2[4];
        u64 binit = splat2(ba1[tid]);
#pragma unroll
        for (int p = 0; p < 4; p++) acc2[p] = binit;

        const float* Bs = &d_B[((size_t)s * NFEAT) * H1D + tid];
#pragma unroll 8
        for (int f = 0; f < NFEAT; f++) {
            u64 bw = splat2(__ldg(&Bs[(size_t)f * H1D]));
            const u64* fp = (const u64*)&sfeatT[f * GPADF];
#pragma unroll
            for (int p = 0; p < 4; p++) fma2(acc2[p], fp[p], bw);
        }
#pragma unroll
        for (int p = 0; p < 4; p++) {
            float lo, hi; unpack2(acc2[p], lo, hi);
            sh1T[tid * GPADF + 2 * p]     = silu(lo);
            sh1T[tid * GPADF + 2 * p + 1] = silu(hi);
        }
    }
    __syncthreads();

    // layer 2: 256 -> 128
    {
        int o2 = tid & 127;
        int half = tid >> 7;
        u64 acc2[2];
        u64 binit = splat2(ba2[o2]);
        acc2[0] = binit; acc2[1] = binit;
#pragma unroll 8
        for (int j = 0; j < H1D; j++) {
            u64 w = splat2(__ldg(&Wa2[j * H2D + o2]));
            const u64* hp = (const u64*)&sh1T[j * GPADF + half * 4];
            fma2(acc2[0], hp[0], w); fma2(acc2[1], hp[1], w);
        }
#pragma unroll
        for (int p = 0; p < 2; p++) {
            float lo, hi; unpack2(acc2[p], lo, hi);
            sh2T[o2 * GPADF + half * 4 + 2 * p]     = silu(lo);
            sh2T[o2 * GPADF + half * 4 + 2 * p + 1] = silu(hi);
        }
    }
    __syncthreads();

    if (tid < GATOMS) {
        double ev = 0.0;
        if (tid < cnt) {
            float e3 = ba3[0];
#pragma unroll 4
            for (int j = 0; j < H2D; j++) e3 += sh2T[j * GPADF + tid] * Wa3[j];
            ev = (double)e3;
        }
        se[tid] = ev;
    }
    __syncthreads();
    if (tid == 0) {
        double ssum = 0.0;
        for (int i = 0; i < GATOMS; i++) ssum += se[i];
        d_partial[g] = ssum;
    }
}

__global__ void k_final(float* out) {
    int lane = threadIdx.x;
    double s = 0.0;
    for (int g = lane; g < MAXG; g += 32) s += d_partial[g];
#pragma unroll
    for (int o = 16; o > 0; o >>= 1) s += __shfl_down_sync(0xffffffffu, s, o);
    if (lane == 0) out[0] = (float)s;
}

// ============================================================================
extern "C" void kernel_launch(void* const* d_in, const int* in_sizes, int n_in,
                              void* d_out, int out_size)
{
    const float* rij = (const float*)d_in[0];
    const float* Wr1 = (const float*)d_in[1];
    const float* br1 = (const float*)d_in[2];
    const float* Wr2 = (const float*)d_in[3];
    const float* br2 = (const float*)d_in[4];
    const float* Ws1 = (const float*)d_in[5];
    const float* bs1 = (const float*)d_in[6];
    const float* Ws2 = (const float*)d_in[7];
    const float* bs2 = (const float*)d_in[8];
    const float* Wa1 = (const float*)d_in[9];
    const float* ba1 = (const float*)d_in[10];
    const float* Wa2 = (const float*)d_in[11];
    const float* ba2 = (const float*)d_in[12];
    const float* Wa3 = (const float*)d_in[13];
    const float* ba3 = (const float*)d_in[14];
    const int* fai = (const int*)d_in[15];
    const int* species = (const int*)d_in[16];
    float* out = (float*)d_out;

    static cudaStream_t sB = 0;
    static cudaEvent_t evFork = 0, evB = 0;
    static int init_done = 0;
    if (!init_done) {
        cudaFuncSetAttribute(k_edge, cudaFuncAttributeMaxDynamicSharedMemorySize,
                             SMEM_EDGE_BYTES);
        cudaFuncSetAttribute(k_atom, cudaFuncAttributeMaxDynamicSharedMemorySize,
                             SMEM_ATOM_BYTES);
        cudaStreamCreateWithFlags(&sB, cudaStreamNonBlocking);
        cudaEventCreateWithFlags(&evFork, cudaEventDisableTiming);
        cudaEventCreateWithFlags(&evB, cudaEventDisableTiming);
        init_done = 1;
    }

    // fork: side stream runs k_group -> k_B concurrently with k_edge/k_atom
    cudaEventRecord(evFork, 0);
    cudaStreamWaitEvent(sB, evFork, 0);
    k_group<<<1, 1024, 0, sB>>>(species, Ws1, bs1, Ws2, bs2);
    k_B<<<dim3(NFEAT, 4), 256, 0, sB>>>(Wa1);
    cudaEventRecord(evB, sB);

    // main stream: edge pipeline
    k_edge<<<EDGES / 128, 256, SMEM_EDGE_BYTES>>>(rij, Wr1, br1, Wr2, br2, fai);
    k_atom<<<NATOM, 128, SMEM_ATOM_BYTES>>>();

    // join: k_head needs d_feat (main) + d_B/groups (side)
    cudaStreamWaitEvent(0, evB, 0);
    k_head<<<MAXG, 256>>>(ba1, Wa2, ba2, Wa3, ba3);
    k_final<<<1, 32>>>(out);
}